// round 1
// baseline (speedup 1.0000x reference)
#include <cuda_runtime.h>
#include <cuda_bf16.h>

// CorrelationLayer: out[b,d,h,w] = (1/sqrt(C)) * sum_c x1[b,c,h,w] * x2pad[b,c,h+di,w+dj]
// d enumerates (di,dj) in row-major over [-4,4]^2, skipping (0,0)  -> 80 disps.
// Shapes: B=8, C=128, H=128, W=192. Output (8, 80, 128, 192) fp32.

#define CC   128
#define HH   128
#define WW   192
#define BB   8
#define PW   64    // pixel tile width per block
#define PH   2     // pixel tile height per block
#define CHS  8     // channels per smem stage
#define TX   16    // threads along x (each covers 4 pixels)
#define NDI  9     // displacement rows, split across threadIdx.y
#define NTHREADS (TX * NDI * PH)   // 288

__global__ __launch_bounds__(NTHREADS, 3)
void corr_kernel(const float* __restrict__ x1,
                 const float* __restrict__ x2,
                 float* __restrict__ out)
{
    __shared__ __align__(16) float s1[CHS][PH][PW];          // x1 tile
    __shared__ __align__(16) float s2[CHS][PH + 8][PW + 8];  // x2 halo tile

    const int tx  = threadIdx.x;   // 0..15
    const int diI = threadIdx.y;   // 0..8  (di = diI - 4)
    const int pz  = threadIdx.z;   // 0..1  (pixel row within tile)
    const int tid = tx + TX * diI + TX * NDI * pz;

    const int w0 = blockIdx.x * PW;
    const int h0 = blockIdx.y * PH;
    const int b  = blockIdx.z;

    float acc[9][4];
    #pragma unroll
    for (int j = 0; j < 9; j++)
        #pragma unroll
        for (int k = 0; k < 4; k++)
            acc[j][k] = 0.0f;

    const int hh = h0 + pz;                 // this thread's output row
    const int r2 = pz + diI;                // x2 halo row = pz + 4 + (diI-4)

    for (int cs = 0; cs < CC; cs += CHS) {
        // ---- cooperative load: x1 tile (CHS*PH*PW floats) ----
        for (int i = tid; i < CHS * PH * PW; i += NTHREADS) {
            int ch   = i / (PH * PW);
            int rem  = i - ch * (PH * PW);
            int r    = rem / PW;
            int cpos = rem - r * PW;
            s1[ch][r][cpos] =
                x1[(((size_t)(b * CC + cs + ch) * HH + (h0 + r)) * WW) + w0 + cpos];
        }
        // ---- cooperative load: x2 halo (CHS*10*72 floats), zero-padded ----
        for (int i = tid; i < CHS * (PH + 8) * (PW + 8); i += NTHREADS) {
            int ch   = i / ((PH + 8) * (PW + 8));
            int rem  = i - ch * ((PH + 8) * (PW + 8));
            int r    = rem / (PW + 8);
            int cpos = rem - r * (PW + 8);
            int hr = h0 - 4 + r;
            int wc = w0 - 4 + cpos;
            float v = 0.0f;
            if ((unsigned)hr < (unsigned)HH && (unsigned)wc < (unsigned)WW)
                v = x2[(((size_t)(b * CC + cs + ch) * HH + hr) * WW) + wc];
            s2[ch][r][cpos] = v;
        }
        __syncthreads();

        // ---- compute CHS channels ----
        #pragma unroll
        for (int ch = 0; ch < CHS; ch++) {
            const float4 a4 = *(const float4*)&s1[ch][pz][4 * tx];
            float a[4] = {a4.x, a4.y, a4.z, a4.w};

            const float4 t0 = *(const float4*)&s2[ch][r2][4 * tx];
            const float4 t1 = *(const float4*)&s2[ch][r2][4 * tx + 4];
            const float4 t2 = *(const float4*)&s2[ch][r2][4 * tx + 8];
            float v[12] = {t0.x, t0.y, t0.z, t0.w,
                           t1.x, t1.y, t1.z, t1.w,
                           t2.x, t2.y, t2.z, t2.w};

            #pragma unroll
            for (int j = 0; j < 9; j++)
                #pragma unroll
                for (int k = 0; k < 4; k++)
                    acc[j][k] += a[k] * v[j + k];
        }
        __syncthreads();
    }

    // ---- epilogue: scale + store (skip center disp) ----
    const float scale = 0.08838834764831845f;  // 1/sqrt(128)
    #pragma unroll
    for (int j = 0; j < 9; j++) {
        int lin = diI * 9 + j;
        if (lin == 40) continue;               // (0,0) displacement
        int d = lin - (lin > 40 ? 1 : 0);
        float4 o;
        o.x = acc[j][0] * scale;
        o.y = acc[j][1] * scale;
        o.z = acc[j][2] * scale;
        o.w = acc[j][3] * scale;
        *(float4*)&out[(((size_t)(b * 80 + d) * HH + hh) * WW) + w0 + 4 * tx] = o;
    }
}

extern "C" void kernel_launch(void* const* d_in, const int* in_sizes, int n_in,
                              void* d_out, int out_size)
{
    const float* x1 = (const float*)d_in[0];
    const float* x2 = (const float*)d_in[1];
    float* out = (float*)d_out;

    dim3 grid(WW / PW, HH / PH, BB);   // (3, 64, 8)
    dim3 block(TX, NDI, PH);           // (16, 9, 2) = 288 threads
    corr_kernel<<<grid, block>>>(x1, x2, out);
}

// round 2
// speedup vs baseline: 2.5196x; 2.5196x over previous
#include <cuda_runtime.h>
#include <cuda_bf16.h>

// CorrelationLayer: out[b,d,h,w] = (1/sqrt(C)) * sum_c x1[b,c,h,w] * x2pad[b,c,h+di,w+dj]
// 80 displacements ((di,dj) in [-4,4]^2 minus (0,0)). B=8, C=128, H=128, W=192, fp32.

#define CC   128
#define HH   128
#define WW   192
#define BB   8
#define PW   64    // pixel tile width per block
#define PH   2     // pixel tile height per block
#define CHS  8     // channels per smem stage
#define TX   16    // threads along x (each covers 4 pixels)
#define NDI  9     // displacement rows, split across threadIdx.y
#define NTHREADS (TX * NDI * PH)       // 288
#define NSTAGES  (CC / CHS)            // 16
#define HALO_H   (PH + 8)              // 10
#define HALO_W   (PW + 8)              // 72
#define S1_ELEMS (CHS * PH * PW)       // 1024 floats
#define S2_ELEMS (CHS * HALO_H * HALO_W) // 5760 floats
#define X2_SLOTS 5                     // 5760/4 float4 / 288 threads

__device__ __forceinline__ unsigned smem_u32(const void* p) {
    return (unsigned)__cvta_generic_to_shared(p);
}
__device__ __forceinline__ void cp16(unsigned dst, const float* src) {
    asm volatile("cp.async.cg.shared.global [%0], [%1], 16;\n" :: "r"(dst), "l"(src));
}
__device__ __forceinline__ void cp_commit() {
    asm volatile("cp.async.commit_group;\n" ::: "memory");
}
template <int N> __device__ __forceinline__ void cp_wait() {
    asm volatile("cp.async.wait_group %0;\n" :: "n"(N) : "memory");
}

__global__ __launch_bounds__(NTHREADS, 2)
void corr_kernel(const float* __restrict__ x1,
                 const float* __restrict__ x2,
                 float* __restrict__ out)
{
    __shared__ __align__(16) float s1[2][CHS][PH][PW];
    __shared__ __align__(16) float s2[2][CHS][HALO_H][HALO_W];

    const int tx  = threadIdx.x;   // 0..15
    const int diI = threadIdx.y;   // 0..8
    const int pz  = threadIdx.z;   // 0..1
    const int tid = tx + TX * (diI + NDI * pz);

    const int w0 = blockIdx.x * PW;
    const int h0 = blockIdx.y * PH;
    const int b  = blockIdx.z;

    // Zero both s2 buffers once: OOB halo entries stay 0 forever.
    {
        float4 z = make_float4(0.f, 0.f, 0.f, 0.f);
        float4* p = (float4*)&s2[0][0][0][0];
        for (int i = tid; i < 2 * S2_ELEMS / 4; i += NTHREADS) p[i] = z;
    }

    // ---- hoisted load-slot setup (loop-invariant across the 16 stages) ----
    // x1: one float4 per thread for tid<256
    const float* g1 = x1;  unsigned s1off = 0;  bool has1 = (tid < 256);
    if (has1) {
        int ch = tid >> 5, r = (tid >> 4) & 1, c4 = tid & 15;
        g1 = x1 + (((size_t)(b * CC + ch) * HH + (h0 + r)) * WW) + w0 + 4 * c4;
        s1off = smem_u32(&s1[0][ch][r][4 * c4]);
    }
    // x2: exactly 5 float4 slots per thread (1440 float4 / 288 threads)
    const float* g2[X2_SLOTS];
    unsigned     s2off[X2_SLOTS];
    bool         pr[X2_SLOTS];
    #pragma unroll
    for (int s = 0; s < X2_SLOTS; s++) {
        int i   = tid + NTHREADS * s;
        int ch  = i / 180;            // 180 float4 per channel (10 rows * 18)
        int rem = i - ch * 180;
        int r   = rem / 18;
        int c4  = rem - r * 18;
        int hr  = h0 - 4 + r;
        int wc  = w0 - 4 + 4 * c4;
        // float4 groups are all-in or all-out of the image (w0 % 4 == 0)
        pr[s] = (hr >= 0) && (hr < HH) && (wc >= 0) && (wc < WW);
        int hrc = pr[s] ? hr : 0;     // keep pointer math sane when OOB
        int wcc = pr[s] ? wc : 0;
        g2[s]    = x2 + (((size_t)(b * CC + ch) * HH + hrc) * WW) + wcc;
        s2off[s] = smem_u32(&s2[0][ch][r][4 * c4]);
    }

    const size_t gstep = (size_t)CHS * HH * WW;   // floats per channel-stage

    float acc[9][4];
    #pragma unroll
    for (int j = 0; j < 9; j++)
        #pragma unroll
        for (int k = 0; k < 4; k++) acc[j][k] = 0.0f;

    const int r2 = pz + diI;                      // x2 halo row for this thread

    // ---- prologue: stage 0 loads into buffer 0 ----
    if (has1) cp16(s1off, g1);
    #pragma unroll
    for (int s = 0; s < X2_SLOTS; s++)
        if (pr[s]) cp16(s2off[s], g2[s]);
    cp_commit();

    #pragma unroll 1
    for (int st = 0; st < NSTAGES; st++) {
        const int bb = st & 1;
        if (st + 1 < NSTAGES) {
            // issue stage st+1 into the other buffer
            const unsigned bofs1 = (bb ^ 1) * (S1_ELEMS * 4);
            const unsigned bofs2 = (bb ^ 1) * (S2_ELEMS * 4);
            if (has1) { g1 += gstep; cp16(s1off + bofs1, g1); }
            #pragma unroll
            for (int s = 0; s < X2_SLOTS; s++) {
                g2[s] += gstep;
                if (pr[s]) cp16(s2off[s] + bofs2, g2[s]);
            }
            cp_commit();
            cp_wait<1>();          // stage st's group has landed
        } else {
            cp_wait<0>();
        }
        __syncthreads();

        const float* p1 = &s1[bb][0][pz][4 * tx];
        const float* p2 = &s2[bb][0][r2][4 * tx];
        #pragma unroll
        for (int ch = 0; ch < CHS; ch++) {
            float4 a4 = *(const float4*)(p1 + ch * (PH * PW));
            float4 t0 = *(const float4*)(p2 + ch * (HALO_H * HALO_W));
            float4 t1 = *(const float4*)(p2 + ch * (HALO_H * HALO_W) + 4);
            float4 t2 = *(const float4*)(p2 + ch * (HALO_H * HALO_W) + 8);
            float a[4]  = {a4.x, a4.y, a4.z, a4.w};
            float v[12] = {t0.x, t0.y, t0.z, t0.w,
                           t1.x, t1.y, t1.z, t1.w,
                           t2.x, t2.y, t2.z, t2.w};
            #pragma unroll
            for (int j = 0; j < 9; j++)
                #pragma unroll
                for (int k = 0; k < 4; k++)
                    acc[j][k] = fmaf(a[k], v[j + k], acc[j][k]);
        }
        __syncthreads();
    }

    // ---- epilogue: scale + store (skip center displacement) ----
    const float scale = 0.08838834764831845f;  // 1/sqrt(128)
    const int hh = h0 + pz;
    #pragma unroll
    for (int j = 0; j < 9; j++) {
        int lin = diI * 9 + j;
        if (lin == 40) continue;               // (0,0)
        int d = lin - (lin > 40 ? 1 : 0);
        float4 o;
        o.x = acc[j][0] * scale;
        o.y = acc[j][1] * scale;
        o.z = acc[j][2] * scale;
        o.w = acc[j][3] * scale;
        *(float4*)&out[(((size_t)(b * 80 + d) * HH + hh) * WW) + w0 + 4 * tx] = o;
    }
}

extern "C" void kernel_launch(void* const* d_in, const int* in_sizes, int n_in,
                              void* d_out, int out_size)
{
    const float* x1 = (const float*)d_in[0];
    const float* x2 = (const float*)d_in[1];
    float* out = (float*)d_out;

    dim3 grid(WW / PW, HH / PH, BB);   // (3, 64, 8)
    dim3 block(TX, NDI, PH);           // (16, 9, 2) = 288 threads
    corr_kernel<<<grid, block>>>(x1, x2, out);
}